// round 15
// baseline (speedup 1.0000x reference)
#include <cuda_runtime.h>
#include <cuda_bf16.h>
#include <math_constants.h>
#include <cstdint>
#include <cstring>

// ---------------- problem constants ----------------
#define BATCH   1024
#define DIM     64
#define NCAND   200000
#define TOPK    10
#define K4      4                  // per-thread in-loop shortlist size
#define K8      8                  // merge-phase per-lane list
#define NT      1563               // ceil(200000/128) tiles of 128 cands
#define NCHUNKS 55                 // tile chunks  (8 x 55 = 440 CTAs = ONE wave at 3/SM)
#define NROWT   8                  // 1024/128 row tiles
#define NENT    (NCHUNKS * 4 * K4) // shortlist entries per row = 880
#define NENT_Q  (NENT / 4)         // 220 per merge-warp quarter
#define MLPB    256                // mlp blocks inside fused kernel

// ---------------- device scratch ----------------
static __device__ __align__(1024) unsigned char g_B[(size_t)NT * 16384];  // SW128-swizzled bf16 cand tiles [128c x 64k]
static __device__ __align__(128)  unsigned char g_A[(size_t)BATCH * 128]; // gathered bf16 user rows
static __device__ uint2 g_p[(size_t)BATCH * NENT];                        // packed (float bits, cand idx)

// ---------------- helpers ----------------
__device__ __forceinline__ uint32_t smem_u32(const void* p) {
    uint32_t a;
    asm("{ .reg .u64 t; cvta.to.shared.u64 t, %1; cvt.u32.u64 %0, t; }" : "=r"(a) : "l"(p));
    return a;
}
__device__ __forceinline__ uint32_t pack_bf16x2(float x, float y) {
    __nv_bfloat16 lo = __float2bfloat16(x);
    __nv_bfloat16 hi = __float2bfloat16(y);
    uint16_t lo16, hi16;
    memcpy(&lo16, &lo, 2);
    memcpy(&hi16, &hi, 2);
    return (uint32_t)lo16 | ((uint32_t)hi16 << 16);
}
__device__ __forceinline__ uint32_t sw128(uint32_t off) {
    return off ^ ((off >> 3) & 0x70);
}
__device__ __forceinline__ void ldsm_x4(uint32_t& r0, uint32_t& r1, uint32_t& r2, uint32_t& r3, uint32_t addr) {
    asm volatile("ldmatrix.sync.aligned.m8n8.x4.shared.b16 {%0,%1,%2,%3}, [%4];"
                 : "=r"(r0), "=r"(r1), "=r"(r2), "=r"(r3) : "r"(addr));
}
__device__ __forceinline__ void mma16816(float& d0, float& d1, float& d2, float& d3,
                                         uint32_t a0, uint32_t a1, uint32_t a2, uint32_t a3,
                                         uint32_t b0, uint32_t b1) {
    asm volatile("mma.sync.aligned.m16n8k16.row.col.f32.bf16.bf16.f32 "
                 "{%0,%1,%2,%3}, {%4,%5,%6,%7}, {%8,%9}, {%0,%1,%2,%3};"
                 : "+f"(d0), "+f"(d1), "+f"(d2), "+f"(d3)
                 : "r"(a0), "r"(a1), "r"(a2), "r"(a3), "r"(b0), "r"(b1));
}
#define CP_ASYNC16(smem, gptr) \
    asm volatile("cp.async.cg.shared.global [%0], [%1], 16;" :: "r"(smem), "l"(gptr))
#define CP_COMMIT() asm volatile("cp.async.commit_group;")
#define CP_WAIT0()  asm volatile("cp.async.wait_group 0;")

// Sorted-descending top-N insert, all constant indices after unroll (register-resident).
template<int N>
__device__ __forceinline__ void insN(float s, int ci, float* v, int* ix) {
    v[N - 1] = s; ix[N - 1] = ci;
    #pragma unroll
    for (int q = N - 1; q > 0; q--) {
        if (v[q] > v[q - 1]) {
            float tv = v[q]; v[q] = v[q - 1]; v[q - 1] = tv;
            int  ti = ix[q]; ix[q] = ix[q - 1]; ix[q - 1] = ti;
        }
    }
}

// order-preserving float->uint transform
__device__ __forceinline__ uint32_t f2ord(float f) {
    uint32_t b = __float_as_uint(f);
    return (b & 0x80000000u) ? ~b : (b | 0x80000000u);
}

// ================= Kernel 0: FUSED convert/pre-tile + gather/MLP =================
// blocks [0, MLPB): mlp on 4 rows each.
// blocks [MLPB, ...): converter, 8 units/thread (MLP=8), fully lane-coalesced.
// Unit = 16B input (one float4) -> 8B bf16 output.
__global__ void __launch_bounds__(256) prep_kernel(
    const int* __restrict__ user_id, const int* __restrict__ movie_id,
    const float* __restrict__ ut, const float* __restrict__ ct,
    const float* __restrict__ W1, const float* __restrict__ b1,
    const float* __restrict__ W2, const float* __restrict__ b2,
    const float* __restrict__ W3, const float* __restrict__ b3,
    float* __restrict__ outUE, float* __restrict__ outCE, float* __restrict__ outR)
{
    const int t = threadIdx.x;

    if (blockIdx.x >= MLPB) {
        const long NBU = (long)NT * 2048;            // B units (16B fp32 -> 8B bf16)
        const long TOTAL = NBU + (long)BATCH * 8;    // + A units
        // warp handles 256 consecutive units; lane takes {i, i+32, ..., i+224}
        const long base = (long)(blockIdx.x - MLPB) * 2048 + (long)(t >> 5) * 256 + (t & 31);

        float4 f[8];
        float4 fa[8];        // second half for A units only
        unsigned char* dst[8];
        int kind[8];         // 0 = skip, 1 = B unit, 2 = A unit

        // ---- load phase: 8 independent, fully coalesced LDG.128 ----
        #pragma unroll
        for (int k = 0; k < 8; k++) {
            const long u = base + (long)k * 32;
            kind[k] = 0;
            dst[k] = nullptr;
            f[k] = make_float4(0.f, 0.f, 0.f, 0.f);
            if (u >= TOTAL) continue;
            if (u < NBU) {
                const long tile = u >> 11;
                const int within = (int)(u & 2047);
                const int r = within >> 4, sub16 = within & 15;
                const long c = tile * 128 + r;
                kind[k] = 1;
                dst[k] = g_B + tile * 16384 + sw128((uint32_t)(r * 128 + sub16 * 8));
                if (c < NCAND)
                    f[k] = *(const float4*)(ct + c * 64 + sub16 * 4);
            } else {
                const long g2 = u - NBU;
                const int urow = (int)(g2 >> 3), sub = (int)(g2 & 7);
                const float4* src = (const float4*)(ut + (long)user_id[urow] * 64 + sub * 8);
                kind[k] = 2;
                f[k] = src[0];
                fa[k] = src[1];
                dst[k] = g_A + (long)urow * 128 + sub * 16;
            }
        }

        // ---- pack + store phase ----
        #pragma unroll
        for (int k = 0; k < 8; k++) {
            if (kind[k] == 1) {
                uint2 out;
                out.x = pack_bf16x2(f[k].x, f[k].y);
                out.y = pack_bf16x2(f[k].z, f[k].w);
                *(uint2*)dst[k] = out;
            } else if (kind[k] == 2) {
                uint4 out;
                out.x = pack_bf16x2(f[k].x, f[k].y);
                out.y = pack_bf16x2(f[k].z, f[k].w);
                out.z = pack_bf16x2(fa[k].x, fa[k].y);
                out.w = pack_bf16x2(fa[k].z, fa[k].w);
                *(uint4*)dst[k] = out;
            }
        }
        return;
    }

    // ---------------- mlp part ----------------
    __shared__ float xs[4][128];
    __shared__ float h1s[4][256];
    __shared__ float h2s[4][128];
    __shared__ int uid[4], mid[4];

    const int rbase = blockIdx.x * 4;

    if (t < 4) { uid[t] = user_id[rbase + t]; mid[t] = movie_id[rbase + t]; }
    __syncthreads();

    for (int idx = t; idx < 4 * 128; idx += 256) {
        int r = idx >> 7, k = idx & 127;
        float v;
        if (k < 64) {
            v = ut[(long)uid[r] * DIM + k];
            outUE[(long)(rbase + r) * DIM + k] = v;
        } else {
            v = ct[(long)mid[r] * DIM + (k - 64)];
            outCE[(long)(rbase + r) * DIM + (k - 64)] = v;
        }
        xs[r][k] = v;
    }
    __syncthreads();

    {
        float acc[4];
        float bb = b1[t];
        #pragma unroll
        for (int r = 0; r < 4; r++) acc[r] = bb;
        #pragma unroll 8
        for (int k = 0; k < 128; k++) {
            float w = W1[k * 256 + t];
            #pragma unroll
            for (int r = 0; r < 4; r++) acc[r] += xs[r][k] * w;
        }
        #pragma unroll
        for (int r = 0; r < 4; r++) h1s[r][t] = fmaxf(acc[r], 0.0f);
    }
    __syncthreads();

    if (t < 128) {
        float acc[4];
        float bb = b2[t];
        #pragma unroll
        for (int r = 0; r < 4; r++) acc[r] = bb;
        #pragma unroll 8
        for (int k = 0; k < 256; k++) {
            float w = W2[k * 128 + t];
            #pragma unroll
            for (int r = 0; r < 4; r++) acc[r] += h1s[r][k] * w;
        }
        #pragma unroll
        for (int r = 0; r < 4; r++) h2s[r][t] = fmaxf(acc[r], 0.0f);
    }
    __syncthreads();

    if (t < 4) {
        float s = b3[0];
        #pragma unroll 8
        for (int k = 0; k < 128; k++) s += h2s[t][k] * W3[k];
        outR[rbase + t] = s;
    }
}

// ================= Kernel 1: HMMA GEMM + screened register top-4 =================
// grid (8 rowtiles, 55 chunks) = 440 CTAs = ONE full wave at 3 CTAs/SM.
// 4 buffers / 2-tile groups. Swizzle factored into lane-constant sx[s].
__global__ void __launch_bounds__(256, 3) gemm_topk_kernel()
{
    extern __shared__ __align__(1024) unsigned char sBd[];   // 4 * 16384

    const int tid = threadIdx.x;
    const int wid = tid >> 5;
    const int lane = tid & 31;
    const int rowtile = blockIdx.x;
    const int chunk = blockIdx.y;

    // 23 chunks of 29 tiles, 32 chunks of 28 tiles: 23*29 + 32*28 = 1563
    const int t_begin = chunk * 28 + min(chunk, 23);
    const int t_end = (chunk + 1) * 28 + min(chunk + 1, 23);
    const int ntiles = t_end - t_begin;
    const int ngroups = (ntiles + 1) >> 1;

    uint32_t sbuf[4];
    #pragma unroll
    for (int b = 0; b < 4; b++) sbuf[b] = smem_u32(sBd + b * 16384);

    // ---- stage A into buf0, build register A-fragments ----
    {
        const uint4* asrc = (const uint4*)(g_A + (size_t)rowtile * 128 * 128);
        uint4* adst = (uint4*)sBd;
        #pragma unroll
        for (int p = 0; p < 4; p++)
            adst[p * 256 + tid] = asrc[p * 256 + tid];
    }
    __syncthreads();

    uint32_t af[4][4];
    {
        const int g2 = lane >> 3;
        const int mrow = wid * 16 + (g2 & 1) * 8 + (lane & 7);
        const int kb = (g2 >> 1) * 16;
        #pragma unroll
        for (int s = 0; s < 4; s++) {
            uint32_t addr = sbuf[0] + (uint32_t)(mrow * 128 + s * 32 + kb);
            ldsm_x4(af[s][0], af[s][1], af[s][2], af[s][3], addr);
        }
    }
    __syncthreads();   // A reads done before group-0 prefetch overwrites buf0

    // ---- sorted top-4 per thread per row-half (descending; [3] = current min) ----
    float vLo[K4], vHi[K4];
    int   iLo[K4], iHi[K4];
    #pragma unroll
    for (int j = 0; j < K4; j++) {
        vLo[j] = -CUDART_INF_F; vHi[j] = -CUDART_INF_F;
        iLo[j] = 0x7fffffff;    iHi[j] = 0x7fffffff;
    }

    const int bg2 = lane >> 3;
    const int b_nloc = ((bg2 >> 1) & 1) * 8 + (lane & 7);
    const int b_kb = (bg2 & 1) * 16;
    const int ccol = 2 * (lane & 3);

    // lane-constant swizzled k-step offsets
    uint32_t sx[4];
    {
        const uint32_t X = (uint32_t)((lane & 7) << 4);
        #pragma unroll
        for (int s = 0; s < 4; s++)
            sx[s] = ((uint32_t)(s * 32 + b_kb)) ^ X;
    }
    const uint32_t bnl128 = (uint32_t)(b_nloc * 128);

    // ---- prefetch group 0 (tiles 0,1 -> bufs 0,1) ----
    #pragma unroll
    for (int w = 0; w < 2; w++) {
        if (w < ntiles) {
            const char* src = (const char*)(g_B + (size_t)(t_begin + w) * 16384);
            #pragma unroll
            for (int p = 0; p < 4; p++)
                CP_ASYNC16(sbuf[w] + (uint32_t)(p * 4096 + tid * 16), src + p * 4096 + tid * 16);
        }
    }
    CP_COMMIT();

    for (int g = 0; g < ngroups; g++) {
        CP_WAIT0();          // group g landed (only pending group)
        __syncthreads();     // visibility + all warps done with group g-1 (its buf pair = target below)

        // prefetch group g+1 into pair (g+1)&1
        {
            const int pr = ((g + 1) & 1) * 2;
            #pragma unroll
            for (int w = 0; w < 2; w++) {
                const int tl = 2 * (g + 1) + w;
                if (tl < ntiles) {
                    const char* src = (const char*)(g_B + (size_t)(t_begin + tl) * 16384);
                    #pragma unroll
                    for (int p = 0; p < 4; p++)
                        CP_ASYNC16(sbuf[pr + w] + (uint32_t)(p * 4096 + tid * 16), src + p * 4096 + tid * 16);
                }
            }
            CP_COMMIT();
        }

        // ---- compute the 2 tiles of group g ----
        #pragma unroll 1
        for (int tt = 0; tt < 2; tt++) {
            const int ti_ = 2 * g + tt;
            if (ti_ >= ntiles) break;
            const uint32_t bsn = sbuf[(g & 1) * 2 + tt] + bnl128;   // lane base for this tile
            const int tilec0 = (t_begin + ti_) * 128;

            #pragma unroll
            for (int q = 0; q < 4; q++) {
                float acc[4][4];
                #pragma unroll
                for (int j = 0; j < 4; j++)
                    #pragma unroll
                    for (int e = 0; e < 4; e++) acc[j][e] = 0.0f;

                #pragma unroll
                for (int s = 0; s < 4; s++) {
                    #pragma unroll
                    for (int p = 0; p < 2; p++) {
                        uint32_t addr = bsn + sx[s] + (uint32_t)(q * 4096 + p * 2048);
                        uint32_t b0, b1, b2, b3;
                        ldsm_x4(b0, b1, b2, b3, addr);
                        mma16816(acc[2 * p][0], acc[2 * p][1], acc[2 * p][2], acc[2 * p][3],
                                 af[s][0], af[s][1], af[s][2], af[s][3], b0, b1);
                        mma16816(acc[2 * p + 1][0], acc[2 * p + 1][1], acc[2 * p + 1][2], acc[2 * p + 1][3],
                                 af[s][0], af[s][1], af[s][2], af[s][3], b2, b3);
                    }
                }

                const int cbase = tilec0 + q * 32;

                // screening maxes (branch-free), then ONE branch per row-half
                float mLo = acc[0][0], mHi = acc[0][2];
                #pragma unroll
                for (int j = 0; j < 4; j++) {
                    mLo = fmaxf(mLo, fmaxf(acc[j][0], acc[j][1]));
                    mHi = fmaxf(mHi, fmaxf(acc[j][2], acc[j][3]));
                }
                if (mLo > vLo[K4 - 1]) {
                    #pragma unroll
                    for (int j = 0; j < 4; j++) {
                        const int c0 = cbase + j * 8 + ccol;
                        if (acc[j][0] > vLo[K4 - 1]) insN<K4>(acc[j][0], c0,     vLo, iLo);
                        if (acc[j][1] > vLo[K4 - 1]) insN<K4>(acc[j][1], c0 + 1, vLo, iLo);
                    }
                }
                if (mHi > vHi[K4 - 1]) {
                    #pragma unroll
                    for (int j = 0; j < 4; j++) {
                        const int c0 = cbase + j * 8 + ccol;
                        if (acc[j][2] > vHi[K4 - 1]) insN<K4>(acc[j][2], c0,     vHi, iHi);
                        if (acc[j][3] > vHi[K4 - 1]) insN<K4>(acc[j][3], c0 + 1, vHi, iHi);
                    }
                }
            }
        }
    }

    // ---- dump shortlists: [row][chunk][c*4 + j] packed ----
    {
        const int c = lane & 3;
        const int rowLo = rowtile * 128 + wid * 16 + (lane >> 2);
        const int rowHi = rowLo + 8;
        const long baseLo = ((long)rowLo * NCHUNKS + chunk) * (4 * K4) + c * K4;
        const long baseHi = ((long)rowHi * NCHUNKS + chunk) * (4 * K4) + c * K4;
        #pragma unroll
        for (int j = 0; j < K4; j++) {
            g_p[baseLo + j] = make_uint2(__float_as_uint(vLo[j]), (uint32_t)iLo[j]);
            g_p[baseHi + j] = make_uint2(__float_as_uint(vHi[j]), (uint32_t)iHi[j]);
        }
    }
}

// ================= Kernel 2: merge shortlists + exact fp32 rescore =================
// 512 blocks x 256 threads: 2 rows/block, 4 warps/row (each scans a quarter).
// Each warp extracts its quarter's top-16 (>= 13 > max # of bf16-jitter competitors
// of any true top-10 item, so no true top-10 can be excluded). Union 64, exact rescore.
__global__ void __launch_bounds__(256) merge_kernel(
    const int* __restrict__ user_id,
    const float* __restrict__ ut, const float* __restrict__ ct,
    float* __restrict__ outP)
{
    __shared__ float su[2][64];
    __shared__ int   scand[2][64];
    __shared__ float ssc[2][64];

    const int wid = threadIdx.x >> 5;
    const int lane = threadIdx.x & 31;
    const int row2 = wid >> 2;            // 0..1
    const int qtr = wid & 3;              // 0..3
    const int row = blockIdx.x * 2 + row2;

    if (qtr == 0) {
        const float* urow = ut + (long)user_id[row] * 64;
        su[row2][lane] = urow[lane];
        su[row2][lane + 32] = urow[lane + 32];
    }

    // phase 1: per-warp scan over its quarter, 4 batched loads per iteration
    float tv[K8]; int ti[K8];
    #pragma unroll
    for (int j = 0; j < K8; j++) { tv[j] = -CUDART_INF_F; ti[j] = 0x7fffffff; }
    const long base = (long)row * NENT + (long)qtr * NENT_Q;
    for (int e0 = lane; e0 < NENT_Q; e0 += 128) {
        uint2 pv[4];
        #pragma unroll
        for (int k = 0; k < 4; k++) {
            const int e = e0 + k * 32;
            pv[k] = (e < NENT_Q) ? g_p[base + e] : make_uint2(0u, 0x7fffffffu);
        }
        #pragma unroll
        for (int k = 0; k < 4; k++) {
            float v = __uint_as_float(pv[k].x);
            if (v > tv[K8 - 1]) {
                int idx = (int)pv[k].y;
                if (idx < NCAND) insN<K8>(v, idx, tv, ti);
            }
        }
    }

    // phase 2: 16-round max extraction from per-lane sorted lists -> 16 cands per quarter
    {
        float h = tv[0];
        #pragma unroll 1
        for (int r = 0; r < 16; r++) {
            float m = h;
            #pragma unroll
            for (int d = 16; d > 0; d >>= 1)
                m = fmaxf(m, __shfl_xor_sync(0xFFFFFFFFu, m, d));
            unsigned msk = __ballot_sync(0xFFFFFFFFu, h == m);
            int owner = __ffs(msk) - 1;
            if (lane == owner) {
                scand[row2][qtr * 16 + r] = ti[0];
                #pragma unroll
                for (int q = 0; q < K8 - 1; q++) { tv[q] = tv[q + 1]; ti[q] = ti[q + 1]; }
                tv[K8 - 1] = -CUDART_INF_F;
                h = tv[0];
            }
        }
    }
    __syncthreads();

    // phase 3: warps qtr 0,1 rescore the 64-candidate union exactly (fp32)
    if (qtr < 2) {
        const int slot = qtr * 32 + lane;
        const int c = scand[row2][slot];
        float s = -CUDART_INF_F;
        if (c >= 0 && c < NCAND) {
            const float* crow = ct + (long)c * 64;
            s = 0.0f;
            #pragma unroll 8
            for (int k = 0; k < 64; k++) s += su[row2][k] * crow[k];
        }
        ssc[row2][slot] = s;
    }
    __syncthreads();

    // phase 4: warp qtr==0 does 10 rounds of packed-key max over 64 entries
    if (qtr == 0) {
        const int c0 = scand[row2][lane];
        const int c1 = scand[row2][lane + 32];
        unsigned long long k0 = ((unsigned long long)f2ord(ssc[row2][lane]) << 32) |
                                (unsigned long long)(0xFFFFFFFFu - (uint32_t)c0);
        unsigned long long k1 = ((unsigned long long)f2ord(ssc[row2][lane + 32]) << 32) |
                                (unsigned long long)(0xFFFFFFFFu - (uint32_t)c1);
        #pragma unroll 1
        for (int r = 0; r < TOPK; r++) {
            unsigned long long m = (k0 > k1) ? k0 : k1;
            #pragma unroll
            for (int d = 16; d > 0; d >>= 1) {
                unsigned long long o = __shfl_xor_sync(0xFFFFFFFFu, m, d);
                if (o > m) m = o;
            }
            if (k0 == m) k0 = 0; else if (k1 == m) k1 = 0;   // keys distinct (unique cands)
            if (lane == 0) {
                uint32_t ci = 0xFFFFFFFFu - (uint32_t)(m & 0xFFFFFFFFu);
                outP[(long)row * TOPK + r] = (float)ci;
            }
        }
    }
}

// ================= launch =================
extern "C" void kernel_launch(void* const* d_in, const int* in_sizes, int n_in,
                              void* d_out, int out_size)
{
    const int*   user_id  = (const int*)d_in[0];
    const int*   movie_id = (const int*)d_in[1];
    const float* ut       = (const float*)d_in[2];
    const float* ct       = (const float*)d_in[3];
    const float* W1       = (const float*)d_in[4];
    const float* b1       = (const float*)d_in[5];
    const float* W2       = (const float*)d_in[6];
    const float* b2       = (const float*)d_in[7];
    const float* W3       = (const float*)d_in[8];
    const float* b3       = (const float*)d_in[9];

    float* out   = (float*)d_out;
    float* outUE = out;
    float* outCE = out + BATCH * DIM;
    float* outR  = out + 2 * BATCH * DIM;
    float* outP  = out + 2 * BATCH * DIM + BATCH;

    // fused convert (8 coalesced 16B units / thread) + A-gather + mlp
    const long convUnits = (long)NT * 2048 + BATCH * 8;
    const int convBlocks = (int)((convUnits + 2047) / 2048);   // 2048 units per block
    prep_kernel<<<MLPB + convBlocks, 256>>>(user_id, movie_id, ut, ct,
                                            W1, b1, W2, b2, W3, b3,
                                            outUE, outCE, outR);

    // gemm + fused screened top-4 (64KB dynamic smem), single full wave
    cudaFuncSetAttribute(gemm_topk_kernel,
                         cudaFuncAttributeMaxDynamicSharedMemorySize, 4 * 16384);
    dim3 g2(NROWT, NCHUNKS);
    gemm_topk_kernel<<<g2, 256, 4 * 16384>>>();

    // merge + exact rescore (4 warps/row)
    merge_kernel<<<BATCH / 2, 256>>>(user_id, ut, ct, outP);
}

// round 16
// speedup vs baseline: 1.0765x; 1.0765x over previous
#include <cuda_runtime.h>
#include <cuda_bf16.h>
#include <math_constants.h>
#include <cstdint>
#include <cstring>

// ---------------- problem constants ----------------
#define BATCH   1024
#define DIM     64
#define NCAND   200000
#define TOPK    10
#define K4      4                  // per-thread in-loop shortlist size
#define K8      8                  // merge-phase per-lane list
#define NT      1563               // ceil(200000/128) tiles of 128 cands
#define NCHUNKS 55                 // tile chunks  (8 x 55 = 440 CTAs = ONE wave at 3/SM)
#define NROWT   8                  // 1024/128 row tiles
#define NENT    (NCHUNKS * 4 * K4) // shortlist entries per row = 880
#define NENT_H  (NENT / 2)         // 440 per merge-warp half
#define MLPB    256                // mlp blocks inside fused kernel

// ---------------- device scratch ----------------
static __device__ __align__(1024) unsigned char g_B[(size_t)NT * 16384];  // SW128-swizzled bf16 cand tiles [128c x 64k]
static __device__ __align__(128)  unsigned char g_A[(size_t)BATCH * 128]; // gathered bf16 user rows
static __device__ uint2 g_p[(size_t)BATCH * NENT];                        // packed (float bits, cand idx)

// ---------------- helpers ----------------
__device__ __forceinline__ uint32_t smem_u32(const void* p) {
    uint32_t a;
    asm("{ .reg .u64 t; cvta.to.shared.u64 t, %1; cvt.u32.u64 %0, t; }" : "=r"(a) : "l"(p));
    return a;
}
// single-instruction pack: result = (bf16(hi) << 16) | bf16(lo)
__device__ __forceinline__ uint32_t pack_bf16x2(float lo, float hi) {
    uint32_t r;
    asm("cvt.rn.bf16x2.f32 %0, %1, %2;" : "=r"(r) : "f"(hi), "f"(lo));
    return r;
}
__device__ __forceinline__ uint32_t sw128(uint32_t off) {
    return off ^ ((off >> 3) & 0x70);
}
__device__ __forceinline__ void ldsm_x4(uint32_t& r0, uint32_t& r1, uint32_t& r2, uint32_t& r3, uint32_t addr) {
    asm volatile("ldmatrix.sync.aligned.m8n8.x4.shared.b16 {%0,%1,%2,%3}, [%4];"
                 : "=r"(r0), "=r"(r1), "=r"(r2), "=r"(r3) : "r"(addr));
}
__device__ __forceinline__ void mma16816(float& d0, float& d1, float& d2, float& d3,
                                         uint32_t a0, uint32_t a1, uint32_t a2, uint32_t a3,
                                         uint32_t b0, uint32_t b1) {
    asm volatile("mma.sync.aligned.m16n8k16.row.col.f32.bf16.bf16.f32 "
                 "{%0,%1,%2,%3}, {%4,%5,%6,%7}, {%8,%9}, {%0,%1,%2,%3};"
                 : "+f"(d0), "+f"(d1), "+f"(d2), "+f"(d3)
                 : "r"(a0), "r"(a1), "r"(a2), "r"(a3), "r"(b0), "r"(b1));
}
#define CP_ASYNC16(smem, gptr) \
    asm volatile("cp.async.cg.shared.global [%0], [%1], 16;" :: "r"(smem), "l"(gptr))
#define CP_COMMIT() asm volatile("cp.async.commit_group;")
#define CP_WAIT0()  asm volatile("cp.async.wait_group 0;")

// Sorted-descending top-N insert, all constant indices after unroll (register-resident).
template<int N>
__device__ __forceinline__ void insN(float s, int ci, float* v, int* ix) {
    v[N - 1] = s; ix[N - 1] = ci;
    #pragma unroll
    for (int q = N - 1; q > 0; q--) {
        if (v[q] > v[q - 1]) {
            float tv = v[q]; v[q] = v[q - 1]; v[q - 1] = tv;
            int  ti = ix[q]; ix[q] = ix[q - 1]; ix[q - 1] = ti;
        }
    }
}

// order-preserving float->uint transform
__device__ __forceinline__ uint32_t f2ord(float f) {
    uint32_t b = __float_as_uint(f);
    return (b & 0x80000000u) ? ~b : (b | 0x80000000u);
}

// ================= Kernel 0: FUSED convert/pre-tile + gather/MLP =================
// blocks [0, MLPB): mlp on 4 rows each.
// blocks [MLPB, ...): converter. Unit = 16B input (one float4) -> 8B bf16 output.
//   B units: NT*2048 (tile = u>>11, r = (u&2047)>>4, sub16 = u&15). Fully lane-coalesced.
//   A units (after B): 32B input -> 16B output, gathered user rows.
__global__ void __launch_bounds__(256) prep_kernel(
    const int* __restrict__ user_id, const int* __restrict__ movie_id,
    const float* __restrict__ ut, const float* __restrict__ ct,
    const float* __restrict__ W1, const float* __restrict__ b1,
    const float* __restrict__ W2, const float* __restrict__ b2,
    const float* __restrict__ W3, const float* __restrict__ b3,
    float* __restrict__ outUE, float* __restrict__ outCE, float* __restrict__ outR)
{
    const int t = threadIdx.x;

    if (blockIdx.x >= MLPB) {
        const long NBU = (long)NT * 2048;            // B units (16B fp32 -> 8B bf16)
        const long TOTAL = NBU + (long)BATCH * 8;    // + A units
        // warp handles 128 consecutive units; lane takes {i, i+32, i+64, i+96}
        const long base = (long)(blockIdx.x - MLPB) * 1024 + (long)(t >> 5) * 128 + (t & 31);

        float4 f[4];
        float4 fa[4];        // second half for A units only
        unsigned char* dst[4];
        int kind[4];         // 0 = skip, 1 = B unit, 2 = A unit

        // ---- load phase: 4 independent, fully coalesced LDG.128 ----
        #pragma unroll
        for (int k = 0; k < 4; k++) {
            const long u = base + (long)k * 32;
            kind[k] = 0;
            dst[k] = nullptr;
            f[k] = make_float4(0.f, 0.f, 0.f, 0.f);
            if (u >= TOTAL) continue;
            if (u < NBU) {
                const long tile = u >> 11;
                const int within = (int)(u & 2047);
                const int r = within >> 4, sub16 = within & 15;
                const long c = tile * 128 + r;
                kind[k] = 1;
                dst[k] = g_B + tile * 16384 + sw128((uint32_t)(r * 128 + sub16 * 8));
                if (c < NCAND)
                    f[k] = *(const float4*)(ct + c * 64 + sub16 * 4);
            } else {
                const long g2 = u - NBU;
                const int urow = (int)(g2 >> 3), sub = (int)(g2 & 7);
                const float4* src = (const float4*)(ut + (long)user_id[urow] * 64 + sub * 8);
                kind[k] = 2;
                f[k] = src[0];
                fa[k] = src[1];
                dst[k] = g_A + (long)urow * 128 + sub * 16;
            }
        }

        // ---- pack + store phase ----
        #pragma unroll
        for (int k = 0; k < 4; k++) {
            if (kind[k] == 1) {
                uint2 out;
                out.x = pack_bf16x2(f[k].x, f[k].y);
                out.y = pack_bf16x2(f[k].z, f[k].w);
                *(uint2*)dst[k] = out;
            } else if (kind[k] == 2) {
                uint4 out;
                out.x = pack_bf16x2(f[k].x, f[k].y);
                out.y = pack_bf16x2(f[k].z, f[k].w);
                out.z = pack_bf16x2(fa[k].x, fa[k].y);
                out.w = pack_bf16x2(fa[k].z, fa[k].w);
                *(uint4*)dst[k] = out;
            }
        }
        return;
    }

    // ---------------- mlp part ----------------
    __shared__ float xs[4][128];
    __shared__ float h1s[4][256];
    __shared__ float h2s[4][128];
    __shared__ int uid[4], mid[4];

    const int rbase = blockIdx.x * 4;

    if (t < 4) { uid[t] = user_id[rbase + t]; mid[t] = movie_id[rbase + t]; }
    __syncthreads();

    for (int idx = t; idx < 4 * 128; idx += 256) {
        int r = idx >> 7, k = idx & 127;
        float v;
        if (k < 64) {
            v = ut[(long)uid[r] * DIM + k];
            outUE[(long)(rbase + r) * DIM + k] = v;
        } else {
            v = ct[(long)mid[r] * DIM + (k - 64)];
            outCE[(long)(rbase + r) * DIM + (k - 64)] = v;
        }
        xs[r][k] = v;
    }
    __syncthreads();

    {
        float acc[4];
        float bb = b1[t];
        #pragma unroll
        for (int r = 0; r < 4; r++) acc[r] = bb;
        #pragma unroll 8
        for (int k = 0; k < 128; k++) {
            float w = W1[k * 256 + t];
            #pragma unroll
            for (int r = 0; r < 4; r++) acc[r] += xs[r][k] * w;
        }
        #pragma unroll
        for (int r = 0; r < 4; r++) h1s[r][t] = fmaxf(acc[r], 0.0f);
    }
    __syncthreads();

    if (t < 128) {
        float acc[4];
        float bb = b2[t];
        #pragma unroll
        for (int r = 0; r < 4; r++) acc[r] = bb;
        #pragma unroll 8
        for (int k = 0; k < 256; k++) {
            float w = W2[k * 128 + t];
            #pragma unroll
            for (int r = 0; r < 4; r++) acc[r] += h1s[r][k] * w;
        }
        #pragma unroll
        for (int r = 0; r < 4; r++) h2s[r][t] = fmaxf(acc[r], 0.0f);
    }
    __syncthreads();

    if (t < 4) {
        float s = b3[0];
        #pragma unroll 8
        for (int k = 0; k < 128; k++) s += h2s[t][k] * W3[k];
        outR[rbase + t] = s;
    }
}

// ================= Kernel 1: HMMA GEMM + screened register top-4 =================
// grid (8 rowtiles, 55 chunks) = 440 CTAs = ONE full wave at 3 CTAs/SM.
// 4 buffers / 2-tile groups. Swizzle factored into lane-constant sx[s].
__global__ void __launch_bounds__(256, 3) gemm_topk_kernel()
{
    extern __shared__ __align__(1024) unsigned char sBd[];   // 4 * 16384

    const int tid = threadIdx.x;
    const int wid = tid >> 5;
    const int lane = tid & 31;
    const int rowtile = blockIdx.x;
    const int chunk = blockIdx.y;

    // 23 chunks of 29 tiles, 32 chunks of 28 tiles: 23*29 + 32*28 = 1563
    const int t_begin = chunk * 28 + min(chunk, 23);
    const int t_end = (chunk + 1) * 28 + min(chunk + 1, 23);
    const int ntiles = t_end - t_begin;
    const int ngroups = (ntiles + 1) >> 1;

    uint32_t sbuf[4];
    #pragma unroll
    for (int b = 0; b < 4; b++) sbuf[b] = smem_u32(sBd + b * 16384);

    // ---- stage A into buf0, build register A-fragments ----
    {
        const uint4* asrc = (const uint4*)(g_A + (size_t)rowtile * 128 * 128);
        uint4* adst = (uint4*)sBd;
        #pragma unroll
        for (int p = 0; p < 4; p++)
            adst[p * 256 + tid] = asrc[p * 256 + tid];
    }
    __syncthreads();

    uint32_t af[4][4];
    {
        const int g2 = lane >> 3;
        const int mrow = wid * 16 + (g2 & 1) * 8 + (lane & 7);
        const int kb = (g2 >> 1) * 16;
        #pragma unroll
        for (int s = 0; s < 4; s++) {
            uint32_t addr = sbuf[0] + (uint32_t)(mrow * 128 + s * 32 + kb);
            ldsm_x4(af[s][0], af[s][1], af[s][2], af[s][3], addr);
        }
    }
    __syncthreads();   // A reads done before group-0 prefetch overwrites buf0

    // ---- sorted top-4 per thread per row-half (descending; [3] = current min) ----
    float vLo[K4], vHi[K4];
    int   iLo[K4], iHi[K4];
    #pragma unroll
    for (int j = 0; j < K4; j++) {
        vLo[j] = -CUDART_INF_F; vHi[j] = -CUDART_INF_F;
        iLo[j] = 0x7fffffff;    iHi[j] = 0x7fffffff;
    }

    const int bg2 = lane >> 3;
    const int b_nloc = ((bg2 >> 1) & 1) * 8 + (lane & 7);
    const int b_kb = (bg2 & 1) * 16;
    const int ccol = 2 * (lane & 3);

    // lane-constant swizzled k-step offsets
    uint32_t sx[4];
    {
        const uint32_t X = (uint32_t)((lane & 7) << 4);
        #pragma unroll
        for (int s = 0; s < 4; s++)
            sx[s] = ((uint32_t)(s * 32 + b_kb)) ^ X;
    }
    const uint32_t bnl128 = (uint32_t)(b_nloc * 128);

    // ---- prefetch group 0 (tiles 0,1 -> bufs 0,1) ----
    #pragma unroll
    for (int w = 0; w < 2; w++) {
        if (w < ntiles) {
            const char* src = (const char*)(g_B + (size_t)(t_begin + w) * 16384);
            #pragma unroll
            for (int p = 0; p < 4; p++)
                CP_ASYNC16(sbuf[w] + (uint32_t)(p * 4096 + tid * 16), src + p * 4096 + tid * 16);
        }
    }
    CP_COMMIT();

    for (int g = 0; g < ngroups; g++) {
        CP_WAIT0();          // group g landed (only pending group)
        __syncthreads();     // visibility + all warps done with group g-1 (its buf pair = target below)

        // prefetch group g+1 into pair (g+1)&1
        {
            const int pr = ((g + 1) & 1) * 2;
            #pragma unroll
            for (int w = 0; w < 2; w++) {
                const int tl = 2 * (g + 1) + w;
                if (tl < ntiles) {
                    const char* src = (const char*)(g_B + (size_t)(t_begin + tl) * 16384);
                    #pragma unroll
                    for (int p = 0; p < 4; p++)
                        CP_ASYNC16(sbuf[pr + w] + (uint32_t)(p * 4096 + tid * 16), src + p * 4096 + tid * 16);
                }
            }
            CP_COMMIT();
        }

        // ---- compute the 2 tiles of group g ----
        #pragma unroll 1
        for (int tt = 0; tt < 2; tt++) {
            const int ti_ = 2 * g + tt;
            if (ti_ >= ntiles) break;
            const uint32_t bsn = sbuf[(g & 1) * 2 + tt] + bnl128;   // lane base for this tile
            const int tilec0 = (t_begin + ti_) * 128;

            #pragma unroll
            for (int q = 0; q < 4; q++) {
                float acc[4][4];
                #pragma unroll
                for (int j = 0; j < 4; j++)
                    #pragma unroll
                    for (int e = 0; e < 4; e++) acc[j][e] = 0.0f;

                #pragma unroll
                for (int s = 0; s < 4; s++) {
                    #pragma unroll
                    for (int p = 0; p < 2; p++) {
                        uint32_t addr = bsn + sx[s] + (uint32_t)(q * 4096 + p * 2048);
                        uint32_t b0, b1, b2, b3;
                        ldsm_x4(b0, b1, b2, b3, addr);
                        mma16816(acc[2 * p][0], acc[2 * p][1], acc[2 * p][2], acc[2 * p][3],
                                 af[s][0], af[s][1], af[s][2], af[s][3], b0, b1);
                        mma16816(acc[2 * p + 1][0], acc[2 * p + 1][1], acc[2 * p + 1][2], acc[2 * p + 1][3],
                                 af[s][0], af[s][1], af[s][2], af[s][3], b2, b3);
                    }
                }

                const int cbase = tilec0 + q * 32;

                // screening maxes (branch-free), then ONE branch per row-half
                float mLo = acc[0][0], mHi = acc[0][2];
                #pragma unroll
                for (int j = 0; j < 4; j++) {
                    mLo = fmaxf(mLo, fmaxf(acc[j][0], acc[j][1]));
                    mHi = fmaxf(mHi, fmaxf(acc[j][2], acc[j][3]));
                }
                if (mLo > vLo[K4 - 1]) {
                    #pragma unroll
                    for (int j = 0; j < 4; j++) {
                        const int c0 = cbase + j * 8 + ccol;
                        if (acc[j][0] > vLo[K4 - 1]) insN<K4>(acc[j][0], c0,     vLo, iLo);
                        if (acc[j][1] > vLo[K4 - 1]) insN<K4>(acc[j][1], c0 + 1, vLo, iLo);
                    }
                }
                if (mHi > vHi[K4 - 1]) {
                    #pragma unroll
                    for (int j = 0; j < 4; j++) {
                        const int c0 = cbase + j * 8 + ccol;
                        if (acc[j][2] > vHi[K4 - 1]) insN<K4>(acc[j][2], c0,     vHi, iHi);
                        if (acc[j][3] > vHi[K4 - 1]) insN<K4>(acc[j][3], c0 + 1, vHi, iHi);
                    }
                }
            }
        }
    }

    // ---- dump shortlists: [row][chunk][c*4 + j] packed ----
    {
        const int c = lane & 3;
        const int rowLo = rowtile * 128 + wid * 16 + (lane >> 2);
        const int rowHi = rowLo + 8;
        const long baseLo = ((long)rowLo * NCHUNKS + chunk) * (4 * K4) + c * K4;
        const long baseHi = ((long)rowHi * NCHUNKS + chunk) * (4 * K4) + c * K4;
        #pragma unroll
        for (int j = 0; j < K4; j++) {
            g_p[baseLo + j] = make_uint2(__float_as_uint(vLo[j]), (uint32_t)iLo[j]);
            g_p[baseHi + j] = make_uint2(__float_as_uint(vHi[j]), (uint32_t)iHi[j]);
        }
    }
}

// ================= Kernel 2: merge shortlists + exact fp32 rescore =================
// 256 blocks x 256 threads: 4 rows/block, 2 warps/row (each scans half the entries).
__global__ void __launch_bounds__(256) merge_kernel(
    const int* __restrict__ user_id,
    const float* __restrict__ ut, const float* __restrict__ ct,
    float* __restrict__ outP)
{
    __shared__ float su[4][64];
    __shared__ int   scand[4][32];

    const int wid = threadIdx.x >> 5;
    const int lane = threadIdx.x & 31;
    const int row4 = wid >> 1;            // 0..3
    const int half = wid & 1;             // 0..1
    const int row = blockIdx.x * 4 + row4;

    if (half == 0) {
        const float* urow = ut + (long)user_id[row] * 64;
        su[row4][lane] = urow[lane];
        su[row4][lane + 32] = urow[lane + 32];
    }

    // phase 1: per-warp scan over its half, 4 batched loads per iteration (MLP=4)
    float tv[K8]; int ti[K8];
    #pragma unroll
    for (int j = 0; j < K8; j++) { tv[j] = -CUDART_INF_F; ti[j] = 0x7fffffff; }
    const long base = (long)row * NENT + (long)half * NENT_H;
    for (int e0 = lane; e0 < NENT_H; e0 += 128) {
        uint2 pv[4];
        #pragma unroll
        for (int k = 0; k < 4; k++) {
            const int e = e0 + k * 32;
            pv[k] = (e < NENT_H) ? g_p[base + e] : make_uint2(0u, 0x7fffffffu);
        }
        #pragma unroll
        for (int k = 0; k < 4; k++) {
            float v = __uint_as_float(pv[k].x);
            if (v > tv[K8 - 1]) {
                int idx = (int)pv[k].y;
                if (idx < NCAND) insN<K8>(v, idx, tv, ti);
            }
        }
    }

    // phase 2: 16-round max extraction from per-lane sorted lists -> 16 cands per half
    {
        float h = tv[0];
        #pragma unroll 1
        for (int r = 0; r < 16; r++) {
            float m = h;
            #pragma unroll
            for (int d = 16; d > 0; d >>= 1)
                m = fmaxf(m, __shfl_xor_sync(0xFFFFFFFFu, m, d));
            unsigned msk = __ballot_sync(0xFFFFFFFFu, h == m);
            int owner = __ffs(msk) - 1;
            if (lane == owner) {
                scand[row4][half * 16 + r] = ti[0];
                #pragma unroll
                for (int q = 0; q < K8 - 1; q++) { tv[q] = tv[q + 1]; ti[q] = ti[q + 1]; }
                tv[K8 - 1] = -CUDART_INF_F;
                h = tv[0];
            }
        }
    }
    __syncthreads();

    // phase 3: half-0 warp rescores all 32 shortlisted candidates exactly (fp32),
    // then 10 rounds of packed-key warp max -> output.
    if (half == 0) {
        const int c = scand[row4][lane];
        float s = -CUDART_INF_F;
        if (c >= 0 && c < NCAND) {
            const float* crow = ct + (long)c * 64;
            s = 0.0f;
            #pragma unroll 8
            for (int k = 0; k < 64; k++) s += su[row4][k] * crow[k];
        }
        // packed sortable key: (ordered float) << 32 | (~idx)  -> value desc, idx asc
        unsigned long long key = ((unsigned long long)f2ord(s) << 32) |
                                 (unsigned long long)(0xFFFFFFFFu - (uint32_t)c);
        #pragma unroll 1
        for (int r = 0; r < TOPK; r++) {
            unsigned long long m = key;
            #pragma unroll
            for (int d = 16; d > 0; d >>= 1) {
                unsigned long long o = __shfl_xor_sync(0xFFFFFFFFu, m, d);
                if (o > m) m = o;
            }
            if (key == m) key = 0;   // winner retires (unique: candidate ids distinct)
            if (lane == 0) {
                uint32_t ci = 0xFFFFFFFFu - (uint32_t)(m & 0xFFFFFFFFu);
                outP[(long)row * TOPK + r] = (float)ci;
            }
        }
    }
}

// ================= launch =================
extern "C" void kernel_launch(void* const* d_in, const int* in_sizes, int n_in,
                              void* d_out, int out_size)
{
    const int*   user_id  = (const int*)d_in[0];
    const int*   movie_id = (const int*)d_in[1];
    const float* ut       = (const float*)d_in[2];
    const float* ct       = (const float*)d_in[3];
    const float* W1       = (const float*)d_in[4];
    const float* b1       = (const float*)d_in[5];
    const float* W2       = (const float*)d_in[6];
    const float* b2       = (const float*)d_in[7];
    const float* W3       = (const float*)d_in[8];
    const float* b3       = (const float*)d_in[9];

    float* out   = (float*)d_out;
    float* outUE = out;
    float* outCE = out + BATCH * DIM;
    float* outR  = out + 2 * BATCH * DIM;
    float* outP  = out + 2 * BATCH * DIM + BATCH;

    // fused convert (16B-unit, fully coalesced) + A-gather + mlp
    const long convUnits = (long)NT * 2048 + BATCH * 8;
    const int convBlocks = (int)((convUnits + 1023) / 1024);   // 1024 units per block
    prep_kernel<<<MLPB + convBlocks, 256>>>(user_id, movie_id, ut, ct,
                                            W1, b1, W2, b2, W3, b3,
                                            outUE, outCE, outR);

    // gemm + fused screened top-4 (64KB dynamic smem), single full wave
    cudaFuncSetAttribute(gemm_topk_kernel,
                         cudaFuncAttributeMaxDynamicSharedMemorySize, 4 * 16384);
    dim3 g2(NROWT, NCHUNKS);
    gemm_topk_kernel<<<g2, 256, 4 * 16384>>>();

    // merge + exact rescore
    merge_kernel<<<BATCH / 4, 256>>>(user_id, ut, ct, outP);
}